// round 1
// baseline (speedup 1.0000x reference)
#include <cuda_runtime.h>
#include <math.h>

// EdgeDetection: gray -> gauss3x3(sigma=0.8, reflect101) -> scharr x/y (reflect101) -> L2 mag
// Input  [8,3,1024,1024] f32, Output [8,3,1024,1024] f32 (mag replicated over channels)

#define TH 32
#define TW 64
#define GH (TH + 4)   // 36 gray tile height (2-halo)
#define GW (TW + 4)   // 68 gray tile width
#define BH (TH + 2)   // 34 blurred tile height (1-halo)
#define BW (TW + 2)   // 66 blurred tile width
#define NTHREADS 256

__device__ __forceinline__ int reflect101(int v, int n) {
    // valid for |overshoot| <= n-1 (halo here is <=2)
    v = (v < 0) ? -v : v;
    v = (v >= n) ? (2 * n - 2 - v) : v;
    return v;
}

__global__ __launch_bounds__(NTHREADS)
void edge_detect_kernel(const float* __restrict__ x, float* __restrict__ out,
                        int B, int H, int W) {
    __shared__ float g[GH][GW];
    __shared__ float bl[BH][BW];

    const int x0 = blockIdx.x * TW;
    const int y0 = blockIdx.y * TH;
    const int b  = blockIdx.z;
    const int tid = threadIdx.x;

    // Gaussian 1D weights for k=3, sigma=0.8 (normalized); 2D kernel = outer product
    const float e = expf(-0.78125f);        // exp(-1/(2*sigma^2))
    const float s = 1.0f / (2.0f * e + 1.0f);
    const float GA = e * s;                 // edge weight
    const float GB = s;                     // center weight

    const size_t plane = (size_t)H * W;
    const float* Rp = x + (size_t)b * 3 * plane;
    const float* Gp = Rp + plane;
    const float* Bp = Gp + plane;

    // ---- Stage 1: gray with reflect-101 halo into smem ----
    #pragma unroll 4
    for (int idx = tid; idx < GH * GW; idx += NTHREADS) {
        const int i = idx / GW;
        const int j = idx - i * GW;
        const int gy = reflect101(y0 + i - 2, H);
        const int gx = reflect101(x0 + j - 2, W);
        const size_t o = (size_t)gy * W + gx;
        g[i][j] = 0.299f * __ldg(Rp + o) + 0.587f * __ldg(Gp + o) + 0.114f * __ldg(Bp + o);
    }
    __syncthreads();

    // ---- Stage 2: 3x3 Gaussian blur into smem (with 1-halo) ----
    // bl[i][j] corresponds to gray center g[i+1][j+1]
    #pragma unroll 4
    for (int idx = tid; idx < BH * BW; idx += NTHREADS) {
        const int i = idx / BW;
        const int j = idx - i * BW;
        const float corners = g[i][j] + g[i][j + 2] + g[i + 2][j] + g[i + 2][j + 2];
        const float edges   = g[i][j + 1] + g[i + 1][j] + g[i + 1][j + 2] + g[i + 2][j + 1];
        bl[i][j] = GA * (GA * corners + GB * edges) + GB * GB * g[i + 1][j + 1];
    }
    __syncthreads();

    // ---- Stage 3: Scharr X/Y + magnitude, write 3 channel planes ----
    const int lx  = tid & (TW - 1);   // 0..63
    const int ly0 = tid >> 6;         // 0..3
    float* outp = out + (size_t)b * 3 * plane;

    #pragma unroll
    for (int ly = ly0; ly < TH; ly += NTHREADS / TW) {
        const int i = ly + 1, j = lx + 1;
        const float tl = bl[i - 1][j - 1], tc = bl[i - 1][j], tr = bl[i - 1][j + 1];
        const float ml = bl[i][j - 1],                        mr = bl[i][j + 1];
        const float bll = bl[i + 1][j - 1], bc = bl[i + 1][j], br = bl[i + 1][j + 1];
        const float sx = 3.0f * (tr - tl) + 10.0f * (mr - ml) + 3.0f * (br - bll);
        const float sy = 3.0f * (bll - tl) + 10.0f * (bc - tc) + 3.0f * (br - tr);
        const float mag = sqrtf(sx * sx + sy * sy);
        const size_t o = (size_t)(y0 + ly) * W + (x0 + lx);
        outp[o]             = mag;
        outp[o + plane]     = mag;
        outp[o + 2 * plane] = mag;
    }
}

extern "C" void kernel_launch(void* const* d_in, const int* in_sizes, int n_in,
                              void* d_out, int out_size) {
    const float* x = (const float*)d_in[0];
    float* out = (float*)d_out;
    const int B = 8, H = 1024, W = 1024;

    dim3 grid(W / TW, H / TH, B);
    edge_detect_kernel<<<grid, NTHREADS>>>(x, out, B, H, W);
}

// round 2
// speedup vs baseline: 1.0984x; 1.0984x over previous
#include <cuda_runtime.h>
#include <math.h>

// EdgeDetection: gray -> gauss3x3(sigma=0.8) -> scharr x/y -> L2 mag, all reflect-101.
// Separable composite: sx = S5col ⊗ D5row, sy = D5col ⊗ S5row on gray with 2-px
// reflect-101 halo. Vertical pass via per-thread register sliding window.
// Input [8,3,1024,1024] f32, Output same (mag replicated over channels).

#define TW 64
#define TH 64
#define GW 68           // TW + 4 halo
#define GH 68           // TH + 4 halo
#define NTHREADS 256
#define ROWS_PER_THREAD 16   // TH / (NTHREADS / TW)

__device__ __forceinline__ int reflect101(int v, int n) {
    v = (v < 0) ? -v : v;
    v = (v >= n) ? (2 * n - 2 - v) : v;
    return v;
}

__global__ __launch_bounds__(NTHREADS)
void edge_detect_kernel(const float* __restrict__ x, float* __restrict__ out,
                        int H, int W) {
    __shared__ float g[GH][GW];

    const int x0 = blockIdx.x * TW;
    const int y0 = blockIdx.y * TH;
    const int b  = blockIdx.z;
    const int tid = threadIdx.x;

    // 1-D Gaussian [a, b, a] for k=3 sigma=0.8
    const float e  = expf(-0.78125f);
    const float s  = 1.0f / (2.0f * e + 1.0f);
    const float ga = e * s;
    const float gb = s;
    // Smooth5 = conv([a,b,a],[3,10,3]); Deriv5 = conv([a,b,a],[-1,0,1])
    const float w0 = 3.0f * ga;
    const float w1 = 10.0f * ga + 3.0f * gb;
    const float w2 = 6.0f * ga + 10.0f * gb;

    const size_t plane = (size_t)H * W;
    const float* Rp = x + (size_t)b * 3 * plane;
    const float* Gp = Rp + plane;
    const float* Bp = Gp + plane;

    // ---- Stage 1: grayscale into smem with reflect-101 halo of 2 ----
    #pragma unroll 5
    for (int idx = tid; idx < GH * GW; idx += NTHREADS) {
        const int i = idx / GW;
        const int j = idx - i * GW;
        const int gy = reflect101(y0 + i - 2, H);
        const int gx = reflect101(x0 + j - 2, W);
        const size_t o = (size_t)gy * W + gx;
        g[i][j] = 0.299f * __ldg(Rp + o) + 0.587f * __ldg(Gp + o) + 0.114f * __ldg(Bp + o);
    }
    __syncthreads();

    // ---- Stage 2+3: horizontal 5-tap + vertical 5-tap via register ring ----
    const int c  = tid & (TW - 1);          // output column within tile, 0..63
    const int rg = tid >> 6;                // row group 0..3
    const int rbase = rg * ROWS_PER_THREAD; // first local output row

#define HROW(k, HX, HY) do {                                              \
        const float g0 = g[k][c],     g1 = g[k][c + 1], g2 = g[k][c + 2], \
                    g3 = g[k][c + 3], g4 = g[k][c + 4];                   \
        HX = ga * (g4 - g0) + gb * (g3 - g1);                             \
        HY = w0 * (g0 + g4) + w1 * (g1 + g3) + w2 * g2;                   \
    } while (0)

    float hx0, hx1, hx2, hx3, hx4;
    float hy0, hy1, hy2, hy3, hy4;
    HROW(rbase + 0, hx0, hy0);
    HROW(rbase + 1, hx1, hy1);
    HROW(rbase + 2, hx2, hy2);
    HROW(rbase + 3, hx3, hy3);

    float* outp = out + (size_t)b * 3 * plane + (size_t)(y0 + rbase) * W + (x0 + c);

    #pragma unroll
    for (int t = 0; t < ROWS_PER_THREAD; t++) {
        HROW(rbase + t + 4, hx4, hy4);
        const float sx = w0 * (hx0 + hx4) + w1 * (hx1 + hx3) + w2 * hx2;
        const float sy = ga * (hy4 - hy0) + gb * (hy3 - hy1);
        const float mag = sqrtf(sx * sx + sy * sy);
        outp[0]         = mag;
        outp[plane]     = mag;
        outp[2 * plane] = mag;
        outp += W;
        hx0 = hx1; hx1 = hx2; hx2 = hx3; hx3 = hx4;
        hy0 = hy1; hy1 = hy2; hy2 = hy3; hy3 = hy4;
    }
#undef HROW
}

extern "C" void kernel_launch(void* const* d_in, const int* in_sizes, int n_in,
                              void* d_out, int out_size) {
    const float* x = (const float*)d_in[0];
    float* out = (float*)d_out;
    const int B = 8, H = 1024, W = 1024;

    dim3 grid(W / TW, H / TH, B);
    edge_detect_kernel<<<grid, NTHREADS>>>(x, out, H, W);
}